// round 4
// baseline (speedup 1.0000x reference)
#include <cuda_runtime.h>

#define BATCH 32
#define CH 4
#define SEQ 256
#define FD 256
#define SS (SEQ * SEQ)
#define TOTAL_RAND (BATCH * SS * 2u)

// Scratch (static device globals -- no runtime allocation)
__device__ float g_adj[BATCH * SS];                 // binary adjacency, diag forced 1
__device__ float g_rowinv[BATCH * SEQ];             // 1 / rowsum (fp32 RN)
__device__ float g_X[BATCH * CH * SEQ * FD];        // adjn @ features

// ---------------------------------------------------------------------------
// Threefry-2x32 (JAX PRNG), key = (0, 42) from jax.random.key(42)
// FROZEN: decision path is bit-exact vs reference (rel_err == 0.0 in R3).
// ---------------------------------------------------------------------------
__device__ __forceinline__ void threefry(unsigned x0, unsigned x1,
                                         unsigned& o0, unsigned& o1) {
    const unsigned k0 = 0u, k1 = 42u;
    const unsigned ks2 = k0 ^ k1 ^ 0x1BD11BDAu;
#define TFR(v, r) v = ((v << r) | (v >> (32 - r)))
#define QROUND(a, b, c, d)                                   \
    x0 += x1; TFR(x1, a); x1 ^= x0;                          \
    x0 += x1; TFR(x1, b); x1 ^= x0;                          \
    x0 += x1; TFR(x1, c); x1 ^= x0;                          \
    x0 += x1; TFR(x1, d); x1 ^= x0
    x0 += k0;  x1 += k1;
    QROUND(13, 15, 26, 6);
    x0 += k1;  x1 += ks2 + 1u;
    QROUND(17, 29, 16, 24);
    x0 += ks2; x1 += k0 + 2u;
    QROUND(13, 15, 26, 6);
    x0 += k0;  x1 += k1 + 3u;
    QROUND(17, 29, 16, 24);
    x0 += k1;  x1 += ks2 + 4u;
    QROUND(13, 15, 26, 6);
    x0 += ks2; x1 += k0 + 5u;
    o0 = x0; o1 = x1;
#undef QROUND
#undef TFR
}

__device__ __forceinline__ float gumbel_at(unsigned idx) {
    unsigned o0, o1;
    threefry(0u, idx, o0, o1);           // partitionable counter mode (confirmed)
    unsigned bits = o0 ^ o1;
    float f = __uint_as_float((bits >> 9) | 0x3F800000u) - 1.0f;
    float u = fmaxf(1e-10f, f + 1e-10f);
    return -logf(-logf(u));
}

// exact-erf GELU, matching jax.nn.gelu(approximate=False) op order
__device__ __forceinline__ float gelu_exact(float x) {
    float t = __fdiv_rn(x, 1.41421356f);
    return x * (erff(t) + 1.0f) * 0.5f;
}

// ---------------------------------------------------------------------------
// Kernel 1: corr GEMM (full fp32, sequential-k accumulation -- FROZEN) fused
// with MLP + gumbel argmax decision. grid (8,8,32), block (32,8).
// ---------------------------------------------------------------------------
__global__ __launch_bounds__(256) void adj_kernel(
    const float* __restrict__ fm,
    const float* __restrict__ W1, const float* __restrict__ b1,
    const float* __restrict__ W2, const float* __restrict__ b2,
    const float* __restrict__ W3, const float* __restrict__ b3)
{
    __shared__ float As[32][33];
    __shared__ float At[32][33];
    __shared__ float sW1[16], sb1[16], sW2[128], sb2[8], sW3[16], sb3[2];

    const int tx = threadIdx.x, ty = threadIdx.y;
    const int tid = ty * 32 + tx;
    const int b  = blockIdx.z;
    const int s0 = blockIdx.y * 32, t0 = blockIdx.x * 32;

    if (tid < 16) { sW1[tid] = W1[tid]; sb1[tid] = b1[tid]; sW3[tid] = W3[tid]; }
    if (tid >= 32 && tid < 160)  sW2[tid - 32]  = W2[tid - 32];
    if (tid >= 160 && tid < 168) sb2[tid - 160] = b2[tid - 160];
    if (tid >= 168 && tid < 170) sb3[tid - 168] = b3[tid - 168];

    const float* A = fm + (size_t)b * SEQ * FD;
    float acc[4] = {0.f, 0.f, 0.f, 0.f};

    for (int k0 = 0; k0 < FD; k0 += 32) {
        #pragma unroll
        for (int i = 0; i < 4; i++) {
            As[ty + 8 * i][tx] = A[(s0 + ty + 8 * i) * FD + k0 + tx];
            At[ty + 8 * i][tx] = A[(t0 + ty + 8 * i) * FD + k0 + tx];
        }
        __syncthreads();
        #pragma unroll
        for (int k = 0; k < 32; k++) {
            float bv = At[tx][k];
            #pragma unroll
            for (int i = 0; i < 4; i++)
                acc[i] = fmaf(As[ty + 8 * i][k], bv, acc[i]);
        }
        __syncthreads();
    }

    #pragma unroll
    for (int i = 0; i < 4; i++) {
        float c = acc[i];
        float h1[16];
        #pragma unroll
        for (int q = 0; q < 16; q++) h1[q] = gelu_exact(fmaf(c, sW1[q], sb1[q]));
        float h2[8];
        #pragma unroll
        for (int j = 0; j < 8; j++) {
            float p = sb2[j];
            #pragma unroll
            for (int q = 0; q < 16; q++) p = fmaf(h1[q], sW2[q * 8 + j], p);
            h2[j] = gelu_exact(p);
        }
        float l0 = sb3[0], l1 = sb3[1];
        #pragma unroll
        for (int j = 0; j < 8; j++) {
            l0 = fmaf(h2[j], sW3[2 * j + 0], l0);
            l1 = fmaf(h2[j], sW3[2 * j + 1], l1);
        }
        const int sr = s0 + ty + 8 * i;
        const int tc = t0 + tx;
        const unsigned p = (unsigned)b * SS + (unsigned)sr * SEQ + (unsigned)tc;
        float g0 = gumbel_at(2u * p);
        float g1 = gumbel_at(2u * p + 1u);
        float val = (l0 + g0 >= l1 + g1) ? 1.0f : 0.0f;
        if (sr == tc) val = 1.0f;
        g_adj[p] = val;
    }
}

// ---------------------------------------------------------------------------
// Kernel 2: row sums (exact: integer-valued) -> reciprocal
// ---------------------------------------------------------------------------
__global__ __launch_bounds__(256) void rowsum_kernel() {
    const int row = blockIdx.x;  // b*SEQ + s
    float v = g_adj[(size_t)row * SEQ + threadIdx.x];
    #pragma unroll
    for (int o = 16; o > 0; o >>= 1) v += __shfl_xor_sync(0xFFFFFFFFu, v, o);
    __shared__ float sm[8];
    if ((threadIdx.x & 31) == 0) sm[threadIdx.x >> 5] = v;
    __syncthreads();
    if (threadIdx.x == 0) {
        float s = 0.f;
        #pragma unroll
        for (int w = 0; w < 8; w++) s += sm[w];
        g_rowinv[row] = __frcp_rn(s);
    }
}

// ---------------------------------------------------------------------------
// Kernels 3/4: 128x128 tile, BK=16, double-buffered smem, reg-staged loads,
// ONE __syncthreads per k-tile. 8x8 accumulators per thread.
// ---------------------------------------------------------------------------
#define BM 128
#define BN 128
#define BK 16

__global__ __launch_bounds__(256) void prop_kernel(const float* __restrict__ features) {
    const int z = blockIdx.z;            // b*4 + c
    const int b = z >> 2;
    const float* Aadj = g_adj + (size_t)b * SS;
    const float* Bf   = features + (size_t)z * SEQ * FD;
    float* Cx         = g_X + (size_t)z * SEQ * FD;
    const int m0 = blockIdx.y * BM, n0 = blockIdx.x * BN;

    __shared__ float As[2][BK][BM + 4];
    __shared__ float Bs[2][BK][BN + 4];
    __shared__ float rsc[BM];

    const int tid = threadIdx.x;
    if (tid < BM) rsc[tid] = g_rowinv[b * SEQ + m0 + tid];

    // A loads: row = tid>>1 (0..127), k offsets (tid&1)*8 and +4
    const int arow = tid >> 1, ak = (tid & 1) * 8;
    // B loads: k row = tid>>4 (0..15), col = ((tid*2)&31)*4 and +4
    const int brow = tid >> 4, bcol = ((tid * 2) & 31) * 4;
    const int ty = tid >> 4, tx = tid & 15;

    __syncthreads();   // rsc visible

    float acc[8][8];
    #pragma unroll
    for (int i = 0; i < 8; i++)
        #pragma unroll
        for (int j = 0; j < 8; j++) acc[i][j] = 0.f;

    const float rA = rsc[arow];
    float4 a0, a1, b0v, b1v;

    // prologue: load tile 0
    a0  = *reinterpret_cast<const float4*>(&Aadj[(size_t)(m0 + arow) * SEQ + ak]);
    a1  = *reinterpret_cast<const float4*>(&Aadj[(size_t)(m0 + arow) * SEQ + ak + 4]);
    b0v = *reinterpret_cast<const float4*>(&Bf[(size_t)brow * FD + n0 + bcol]);
    b1v = *reinterpret_cast<const float4*>(&Bf[(size_t)brow * FD + n0 + bcol + 4]);

    #pragma unroll 1
    for (int t = 0; t < SEQ / BK; t++) {
        const int buf = t & 1;
        // store staged tile t into buf
        As[buf][ak + 0][arow] = a0.x * rA;
        As[buf][ak + 1][arow] = a0.y * rA;
        As[buf][ak + 2][arow] = a0.z * rA;
        As[buf][ak + 3][arow] = a0.w * rA;
        As[buf][ak + 4][arow] = a1.x * rA;
        As[buf][ak + 5][arow] = a1.y * rA;
        As[buf][ak + 6][arow] = a1.z * rA;
        As[buf][ak + 7][arow] = a1.w * rA;
        *reinterpret_cast<float4*>(&Bs[buf][brow][bcol])     = b0v;
        *reinterpret_cast<float4*>(&Bs[buf][brow][bcol + 4]) = b1v;
        __syncthreads();

        // prefetch tile t+1 (LDG overlaps with the FMA burst below)
        if (t + 1 < SEQ / BK) {
            const int k0 = (t + 1) * BK;
            a0  = *reinterpret_cast<const float4*>(&Aadj[(size_t)(m0 + arow) * SEQ + k0 + ak]);
            a1  = *reinterpret_cast<const float4*>(&Aadj[(size_t)(m0 + arow) * SEQ + k0 + ak + 4]);
            b0v = *reinterpret_cast<const float4*>(&Bf[(size_t)(k0 + brow) * FD + n0 + bcol]);
            b1v = *reinterpret_cast<const float4*>(&Bf[(size_t)(k0 + brow) * FD + n0 + bcol + 4]);
        }

        #pragma unroll
        for (int kk = 0; kk < BK; kk++) {
            float a[8], bb[8];
            #pragma unroll
            for (int i = 0; i < 8; i++) a[i] = As[buf][kk][ty * 8 + i];
            #pragma unroll
            for (int j = 0; j < 8; j++) bb[j] = Bs[buf][kk][tx * 8 + j];
            #pragma unroll
            for (int i = 0; i < 8; i++)
                #pragma unroll
                for (int j = 0; j < 8; j++)
                    acc[i][j] = fmaf(a[i], bb[j], acc[i][j]);
        }
        __syncthreads();   // all reads of buf done before it is overwritten at t+2
    }

    #pragma unroll
    for (int i = 0; i < 8; i++) {
        float* cp = &Cx[(size_t)(m0 + ty * 8 + i) * FD + n0 + tx * 8];
        *reinterpret_cast<float4*>(cp)     = make_float4(acc[i][0], acc[i][1], acc[i][2], acc[i][3]);
        *reinterpret_cast<float4*>(cp + 4) = make_float4(acc[i][4], acc[i][5], acc[i][6], acc[i][7]);
    }
}

__global__ __launch_bounds__(256) void out_kernel(const float* __restrict__ Wl,
                                                  const float* __restrict__ bl,
                                                  float* __restrict__ out) {
    const int m0 = blockIdx.y * BM, n0 = blockIdx.x * BN;  // M = 32768, N = 256

    __shared__ float As[2][BK][BM + 4];
    __shared__ float Bs[2][BK][BN + 4];

    const int tid = threadIdx.x;
    const int arow = tid >> 1, ak = (tid & 1) * 8;
    const int brow = tid >> 4, bcol = ((tid * 2) & 31) * 4;
    const int ty = tid >> 4, tx = tid & 15;

    float acc[8][8];
    #pragma unroll
    for (int i = 0; i < 8; i++)
        #pragma unroll
        for (int j = 0; j < 8; j++) acc[i][j] = 0.f;

    float4 a0, a1, b0v, b1v;
    a0  = *reinterpret_cast<const float4*>(&g_X[(size_t)(m0 + arow) * FD + ak]);
    a1  = *reinterpret_cast<const float4*>(&g_X[(size_t)(m0 + arow) * FD + ak + 4]);
    b0v = *reinterpret_cast<const float4*>(&Wl[(size_t)brow * FD + n0 + bcol]);
    b1v = *reinterpret_cast<const float4*>(&Wl[(size_t)brow * FD + n0 + bcol + 4]);

    #pragma unroll 1
    for (int t = 0; t < FD / BK; t++) {
        const int buf = t & 1;
        As[buf][ak + 0][arow] = a0.x;
        As[buf][ak + 1][arow] = a0.y;
        As[buf][ak + 2][arow] = a0.z;
        As[buf][ak + 3][arow] = a0.w;
        As[buf][ak + 4][arow] = a1.x;
        As[buf][ak + 5][arow] = a1.y;
        As[buf][ak + 6][arow] = a1.z;
        As[buf][ak + 7][arow] = a1.w;
        *reinterpret_cast<float4*>(&Bs[buf][brow][bcol])     = b0v;
        *reinterpret_cast<float4*>(&Bs[buf][brow][bcol + 4]) = b1v;
        __syncthreads();

        if (t + 1 < FD / BK) {
            const int k0 = (t + 1) * BK;
            a0  = *reinterpret_cast<const float4*>(&g_X[(size_t)(m0 + arow) * FD + k0 + ak]);
            a1  = *reinterpret_cast<const float4*>(&g_X[(size_t)(m0 + arow) * FD + k0 + ak + 4]);
            b0v = *reinterpret_cast<const float4*>(&Wl[(size_t)(k0 + brow) * FD + n0 + bcol]);
            b1v = *reinterpret_cast<const float4*>(&Wl[(size_t)(k0 + brow) * FD + n0 + bcol + 4]);
        }

        #pragma unroll
        for (int kk = 0; kk < BK; kk++) {
            float a[8], bb[8];
            #pragma unroll
            for (int i = 0; i < 8; i++) a[i] = As[buf][kk][ty * 8 + i];
            #pragma unroll
            for (int j = 0; j < 8; j++) bb[j] = Bs[buf][kk][tx * 8 + j];
            #pragma unroll
            for (int i = 0; i < 8; i++)
                #pragma unroll
                for (int j = 0; j < 8; j++)
                    acc[i][j] = fmaf(a[i], bb[j], acc[i][j]);
        }
        __syncthreads();
    }

    float blv[8];
    #pragma unroll
    for (int j = 0; j < 8; j++) blv[j] = bl[n0 + tx * 8 + j];

    #pragma unroll
    for (int i = 0; i < 8; i++) {
        float* cp = &out[(size_t)(m0 + ty * 8 + i) * FD + n0 + tx * 8];
        *reinterpret_cast<float4*>(cp)     = make_float4(acc[i][0] + blv[0], acc[i][1] + blv[1],
                                                         acc[i][2] + blv[2], acc[i][3] + blv[3]);
        *reinterpret_cast<float4*>(cp + 4) = make_float4(acc[i][4] + blv[4], acc[i][5] + blv[5],
                                                         acc[i][6] + blv[6], acc[i][7] + blv[7]);
    }
}

// ---------------------------------------------------------------------------
extern "C" void kernel_launch(void* const* d_in, const int* in_sizes, int n_in,
                              void* d_out, int out_size) {
    const float* features = (const float*)d_in[0];
    const float* fm       = (const float*)d_in[1];
    const float* W1       = (const float*)d_in[2];
    const float* b1       = (const float*)d_in[3];
    const float* W2       = (const float*)d_in[4];
    const float* b2       = (const float*)d_in[5];
    const float* W3       = (const float*)d_in[6];
    const float* b3       = (const float*)d_in[7];
    const float* Wl       = (const float*)d_in[8];
    const float* bl       = (const float*)d_in[9];
    float* out            = (float*)d_out;
    (void)in_sizes; (void)n_in; (void)out_size;

    adj_kernel<<<dim3(8, 8, BATCH), dim3(32, 8)>>>(fm, W1, b1, W2, b2, W3, b3);
    rowsum_kernel<<<BATCH * SEQ, 256>>>();
    prop_kernel<<<dim3(2, 2, BATCH * CH), 256>>>(features);
    out_kernel<<<dim3(2, BATCH * CH * SEQ / BM), 256>>>(Wl, bl, out);
}

// round 5
// speedup vs baseline: 1.8931x; 1.8931x over previous
#include <cuda_runtime.h>

#define BATCH 32
#define CH 4
#define SEQ 256
#define FD 256
#define SS (SEQ * SEQ)

__device__ float g_adj[BATCH * SS];
__device__ float g_rowsum[BATCH * SEQ];
__device__ float g_rowinv[BATCH * SEQ];
__device__ float g_X[BATCH * CH * SEQ * FD];

// ---------------------------------------------------------------------------
// Threefry-2x32 (JAX PRNG), key = (0, 42). FROZEN: bit-exact vs reference.
// ---------------------------------------------------------------------------
__device__ __forceinline__ void threefry(unsigned x0, unsigned x1,
                                         unsigned& o0, unsigned& o1) {
    const unsigned k0 = 0u, k1 = 42u;
    const unsigned ks2 = k0 ^ k1 ^ 0x1BD11BDAu;
#define TFR(v, r) v = ((v << r) | (v >> (32 - r)))
#define QROUND(a, b, c, d)                                   \
    x0 += x1; TFR(x1, a); x1 ^= x0;                          \
    x0 += x1; TFR(x1, b); x1 ^= x0;                          \
    x0 += x1; TFR(x1, c); x1 ^= x0;                          \
    x0 += x1; TFR(x1, d); x1 ^= x0
    x0 += k0;  x1 += k1;
    QROUND(13, 15, 26, 6);
    x0 += k1;  x1 += ks2 + 1u;
    QROUND(17, 29, 16, 24);
    x0 += ks2; x1 += k0 + 2u;
    QROUND(13, 15, 26, 6);
    x0 += k0;  x1 += k1 + 3u;
    QROUND(17, 29, 16, 24);
    x0 += k1;  x1 += ks2 + 4u;
    QROUND(13, 15, 26, 6);
    x0 += ks2; x1 += k0 + 5u;
    o0 = x0; o1 = x1;
#undef QROUND
#undef TFR
}

__device__ __forceinline__ float gumbel_at(unsigned idx) {
    unsigned o0, o1;
    threefry(0u, idx, o0, o1);
    unsigned bits = o0 ^ o1;
    float f = __uint_as_float((bits >> 9) | 0x3F800000u) - 1.0f;
    float u = fmaxf(1e-10f, f + 1e-10f);
    return -logf(-logf(u));
}

__device__ __forceinline__ float gelu_exact(float x) {
    float t = __fdiv_rn(x, 1.41421356f);
    return x * (erff(t) + 1.0f) * 0.5f;
}

// ---------------------------------------------------------------------------
// Kernel 1: corr GEMM (fp32 sequential-k -- FROZEN) + MLP + gumbel argmax,
// with fused exact row sums (order-independent integer atomics).
// ---------------------------------------------------------------------------
__global__ __launch_bounds__(256) void adj_kernel(
    const float* __restrict__ fm,
    const float* __restrict__ W1, const float* __restrict__ b1,
    const float* __restrict__ W2, const float* __restrict__ b2,
    const float* __restrict__ W3, const float* __restrict__ b3)
{
    __shared__ float As[32][33];
    __shared__ float At[32][33];
    __shared__ float sW1[16], sb1[16], sW2[128], sb2[8], sW3[16], sb3[2];

    const int tx = threadIdx.x, ty = threadIdx.y;
    const int tid = ty * 32 + tx;
    const int b  = blockIdx.z;
    const int s0 = blockIdx.y * 32, t0 = blockIdx.x * 32;

    if (tid < 16) { sW1[tid] = W1[tid]; sb1[tid] = b1[tid]; sW3[tid] = W3[tid]; }
    if (tid >= 32 && tid < 160)  sW2[tid - 32]  = W2[tid - 32];
    if (tid >= 160 && tid < 168) sb2[tid - 160] = b2[tid - 160];
    if (tid >= 168 && tid < 170) sb3[tid - 168] = b3[tid - 168];

    const float* A = fm + (size_t)b * SEQ * FD;
    float acc[4] = {0.f, 0.f, 0.f, 0.f};

    for (int k0 = 0; k0 < FD; k0 += 32) {
        #pragma unroll
        for (int i = 0; i < 4; i++) {
            As[ty + 8 * i][tx] = A[(s0 + ty + 8 * i) * FD + k0 + tx];
            At[ty + 8 * i][tx] = A[(t0 + ty + 8 * i) * FD + k0 + tx];
        }
        __syncthreads();
        #pragma unroll
        for (int k = 0; k < 32; k++) {
            float bv = At[tx][k];
            #pragma unroll
            for (int i = 0; i < 4; i++)
                acc[i] = fmaf(As[ty + 8 * i][k], bv, acc[i]);
        }
        __syncthreads();
    }

    #pragma unroll
    for (int i = 0; i < 4; i++) {
        float c = acc[i];
        float h1[16];
        #pragma unroll
        for (int q = 0; q < 16; q++) h1[q] = gelu_exact(fmaf(c, sW1[q], sb1[q]));
        float h2[8];
        #pragma unroll
        for (int j = 0; j < 8; j++) {
            float p = sb2[j];
            #pragma unroll
            for (int q = 0; q < 16; q++) p = fmaf(h1[q], sW2[q * 8 + j], p);
            h2[j] = gelu_exact(p);
        }
        float l0 = sb3[0], l1 = sb3[1];
        #pragma unroll
        for (int j = 0; j < 8; j++) {
            l0 = fmaf(h2[j], sW3[2 * j + 0], l0);
            l1 = fmaf(h2[j], sW3[2 * j + 1], l1);
        }
        const int sr = s0 + ty + 8 * i;
        const int tc = t0 + tx;
        const unsigned p = (unsigned)b * SS + (unsigned)sr * SEQ + (unsigned)tc;
        float g0 = gumbel_at(2u * p);
        float g1 = gumbel_at(2u * p + 1u);
        float val = (l0 + g0 >= l1 + g1) ? 1.0f : 0.0f;
        if (sr == tc) val = 1.0f;
        g_adj[p] = val;
        float rp = val;
        #pragma unroll
        for (int o = 16; o > 0; o >>= 1) rp += __shfl_xor_sync(0xFFFFFFFFu, rp, o);
        if (tx == 0) atomicAdd(&g_rowsum[b * SEQ + sr], rp);
    }
}

__global__ void zero_kernel() {
    int i = blockIdx.x * 256 + threadIdx.x;
    if (i < BATCH * SEQ) g_rowsum[i] = 0.f;
}
__global__ void inv_kernel() {
    int i = blockIdx.x * 256 + threadIdx.x;
    if (i < BATCH * SEQ) g_rowinv[i] = __frcp_rn(g_rowsum[i]);
}

// ---------------------------------------------------------------------------
// TF32 tensor-core GEMMs. Block 128x128x32, 8 warps (4m x 2n), warp 32x64.
// ---------------------------------------------------------------------------
__device__ __forceinline__ unsigned tf32b(float x) {
    unsigned u;
    asm("cvt.rna.tf32.f32 %0, %1;" : "=r"(u) : "f"(x));
    return u;
}

__device__ __forceinline__ void mma_tf32(float* d, const unsigned* a, const unsigned* b) {
    asm volatile("mma.sync.aligned.m16n8k8.row.col.f32.tf32.tf32.f32 "
                 "{%0,%1,%2,%3}, {%4,%5,%6,%7}, {%8,%9}, {%0,%1,%2,%3};"
                 : "+f"(d[0]), "+f"(d[1]), "+f"(d[2]), "+f"(d[3])
                 : "r"(a[0]), "r"(a[1]), "r"(a[2]), "r"(a[3]),
                   "r"(b[0]), "r"(b[1]));
}

#define GBK 32
#define GP 136   // 128 + 8 pad: frag-load bank = (8k + m) % 32, conflict-free

__global__ __launch_bounds__(256) void prop_mma(const float* __restrict__ features) {
    __shared__ unsigned As[GBK][GP];   // As[k][m] = tf32(adjn[m][k])
    __shared__ unsigned Bs[GBK][GP];   // Bs[k][n] = tf32(F[k][n])

    const int z = blockIdx.z, b = z >> 2;
    const float* Aadj = g_adj + (size_t)b * SS;
    const float* Bf   = features + (size_t)z * SEQ * FD;
    float* Cx         = g_X + (size_t)z * SEQ * FD;
    const int m0 = blockIdx.y * 128, n0 = blockIdx.x * 128;

    const int tid = threadIdx.x;
    const int lane = tid & 31, wid = tid >> 5;
    const int g = lane >> 2, t = lane & 3;
    const int wm = (wid >> 1) * 32, wn = (wid & 1) * 64;
    const int lm = tid >> 1, lk = (tid & 1) * 16;
    const int lkb = tid >> 3, ln = (tid & 7) * 16;
    const float rA = g_rowinv[b * SEQ + m0 + lm];

    float acc[2][8][4] = {};

    for (int kt = 0; kt < SEQ; kt += GBK) {
        #pragma unroll
        for (int j = 0; j < 4; j++) {
            float4 v = *reinterpret_cast<const float4*>(
                &Aadj[(size_t)(m0 + lm) * SEQ + kt + lk + 4 * j]);
            As[lk + 4*j + 0][lm] = tf32b(v.x * rA);
            As[lk + 4*j + 1][lm] = tf32b(v.y * rA);
            As[lk + 4*j + 2][lm] = tf32b(v.z * rA);
            As[lk + 4*j + 3][lm] = tf32b(v.w * rA);
        }
        #pragma unroll
        for (int j = 0; j < 4; j++) {
            float4 v = *reinterpret_cast<const float4*>(
                &Bf[(size_t)(kt + lkb) * FD + n0 + ln + 4 * j]);
            uint4 w;
            w.x = tf32b(v.x); w.y = tf32b(v.y); w.z = tf32b(v.z); w.w = tf32b(v.w);
            *reinterpret_cast<uint4*>(&Bs[lkb][ln + 4 * j]) = w;
        }
        __syncthreads();
        #pragma unroll
        for (int kb = 0; kb < 4; kb++) {
            unsigned a[2][4], bfr[8][2];
            #pragma unroll
            for (int mt = 0; mt < 2; mt++) {
                const int mb = wm + mt * 16;
                a[mt][0] = As[kb*8 + t    ][mb + g];
                a[mt][1] = As[kb*8 + t    ][mb + g + 8];
                a[mt][2] = As[kb*8 + t + 4][mb + g];
                a[mt][3] = As[kb*8 + t + 4][mb + g + 8];
            }
            #pragma unroll
            for (int nt = 0; nt < 8; nt++) {
                const int nb = wn + nt * 8;
                bfr[nt][0] = Bs[kb*8 + t    ][nb + g];
                bfr[nt][1] = Bs[kb*8 + t + 4][nb + g];
            }
            #pragma unroll
            for (int mt = 0; mt < 2; mt++)
                #pragma unroll
                for (int nt = 0; nt < 8; nt++)
                    mma_tf32(acc[mt][nt], a[mt], bfr[nt]);
        }
        __syncthreads();
    }

    #pragma unroll
    for (int mt = 0; mt < 2; mt++) {
        const int r0 = m0 + wm + mt * 16 + g;
        #pragma unroll
        for (int nt = 0; nt < 8; nt++) {
            const int c = n0 + wn + nt * 8 + 2 * t;
            *reinterpret_cast<float2*>(&Cx[(size_t)r0 * FD + c]) =
                make_float2(acc[mt][nt][0], acc[mt][nt][1]);
            *reinterpret_cast<float2*>(&Cx[(size_t)(r0 + 8) * FD + c]) =
                make_float2(acc[mt][nt][2], acc[mt][nt][3]);
        }
    }
}

__global__ __launch_bounds__(256) void out_mma(const float* __restrict__ Wl,
                                               const float* __restrict__ bl,
                                               float* __restrict__ out) {
    __shared__ unsigned As[GBK][GP];
    __shared__ unsigned Bs[GBK][GP];

    const int m0 = blockIdx.y * 128, n0 = blockIdx.x * 128;

    const int tid = threadIdx.x;
    const int lane = tid & 31, wid = tid >> 5;
    const int g = lane >> 2, t = lane & 3;
    const int wm = (wid >> 1) * 32, wn = (wid & 1) * 64;
    const int lm = tid >> 1, lk = (tid & 1) * 16;
    const int lkb = tid >> 3, ln = (tid & 7) * 16;

    float acc[2][8][4] = {};

    for (int kt = 0; kt < FD; kt += GBK) {
        #pragma unroll
        for (int j = 0; j < 4; j++) {
            float4 v = *reinterpret_cast<const float4*>(
                &g_X[(size_t)(m0 + lm) * FD + kt + lk + 4 * j]);
            As[lk + 4*j + 0][lm] = tf32b(v.x);
            As[lk + 4*j + 1][lm] = tf32b(v.y);
            As[lk + 4*j + 2][lm] = tf32b(v.z);
            As[lk + 4*j + 3][lm] = tf32b(v.w);
        }
        #pragma unroll
        for (int j = 0; j < 4; j++) {
            float4 v = *reinterpret_cast<const float4*>(
                &Wl[(size_t)(kt + lkb) * FD + n0 + ln + 4 * j]);
            uint4 w;
            w.x = tf32b(v.x); w.y = tf32b(v.y); w.z = tf32b(v.z); w.w = tf32b(v.w);
            *reinterpret_cast<uint4*>(&Bs[lkb][ln + 4 * j]) = w;
        }
        __syncthreads();
        #pragma unroll
        for (int kb = 0; kb < 4; kb++) {
            unsigned a[2][4], bfr[8][2];
            #pragma unroll
            for (int mt = 0; mt < 2; mt++) {
                const int mb = wm + mt * 16;
                a[mt][0] = As[kb*8 + t    ][mb + g];
                a[mt][1] = As[kb*8 + t    ][mb + g + 8];
                a[mt][2] = As[kb*8 + t + 4][mb + g];
                a[mt][3] = As[kb*8 + t + 4][mb + g + 8];
            }
            #pragma unroll
            for (int nt = 0; nt < 8; nt++) {
                const int nb = wn + nt * 8;
                bfr[nt][0] = Bs[kb*8 + t    ][nb + g];
                bfr[nt][1] = Bs[kb*8 + t + 4][nb + g];
            }
            #pragma unroll
            for (int mt = 0; mt < 2; mt++)
                #pragma unroll
                for (int nt = 0; nt < 8; nt++)
                    mma_tf32(acc[mt][nt], a[mt], bfr[nt]);
        }
        __syncthreads();
    }

    #pragma unroll
    for (int mt = 0; mt < 2; mt++) {
        const int r0 = m0 + wm + mt * 16 + g;
        #pragma unroll
        for (int nt = 0; nt < 8; nt++) {
            const int c = n0 + wn + nt * 8 + 2 * t;
            float bl0 = bl[c], bl1 = bl[c + 1];
            *reinterpret_cast<float2*>(&out[(size_t)r0 * FD + c]) =
                make_float2(acc[mt][nt][0] + bl0, acc[mt][nt][1] + bl1);
            *reinterpret_cast<float2*>(&out[(size_t)(r0 + 8) * FD + c]) =
                make_float2(acc[mt][nt][2] + bl0, acc[mt][nt][3] + bl1);
        }
    }
}

// ---------------------------------------------------------------------------
extern "C" void kernel_launch(void* const* d_in, const int* in_sizes, int n_in,
                              void* d_out, int out_size) {
    const float* features = (const float*)d_in[0];
    const float* fm       = (const float*)d_in[1];
    const float* W1       = (const float*)d_in[2];
    const float* b1       = (const float*)d_in[3];
    const float* W2       = (const float*)d_in[4];
    const float* b2       = (const float*)d_in[5];
    const float* W3       = (const float*)d_in[6];
    const float* b3       = (const float*)d_in[7];
    const float* Wl       = (const float*)d_in[8];
    const float* bl       = (const float*)d_in[9];
    float* out            = (float*)d_out;
    (void)in_sizes; (void)n_in; (void)out_size;

    zero_kernel<<<(BATCH * SEQ + 255) / 256, 256>>>();
    adj_kernel<<<dim3(8, 8, BATCH), dim3(32, 8)>>>(fm, W1, b1, W2, b2, W3, b3);
    inv_kernel<<<(BATCH * SEQ + 255) / 256, 256>>>();
    prop_mma<<<dim3(2, 2, BATCH * CH), 256>>>(features);
    out_mma<<<dim3(2, BATCH * CH * SEQ / 128), 256>>>(Wl, bl, out);
}